// round 7
// baseline (speedup 1.0000x reference)
#include <cuda_runtime.h>
#include <cstdint>

// PackedViterbi (logsumexp semiring) forward — warp-specialized exp-domain relay.
// theta: [T=256, B=32, S=128, S=128] fp32.  out: [B=32] fp32.
//
// 32 clusters x 4 CTAs (one per batch). 192 threads per CTA:
//   warps 0-1 (64 thr): CONSUMERS — run the serial V recurrence. Per step:
//     poll 2 tagged exp-domain DSMEM slots per lane, renorm by slot-0 exponent,
//     64-thread barrier, half-row dot (64 FMA), shfl, fan-out send to 4 ranks.
//   warps 2-5 (128 thr): PRODUCERS — LDG theta (2 stages ahead, registers),
//     E = exp2(theta*log2e), STS into an EP=4 padded smem ring. Named-barrier
//     full/empty handshake with consumers. All MUFU/HBM work is off the chain.

#define NT    256
#define NB    32
#define NS    128
#define SUBS  4
#define NTHR  192
#define NCONS 64
#define EP    4
#define ESTR4 33                  // float4 per E row (132 floats, +4 pad)
#define ESZ4  (32 * ESTR4)        // 1056 float4 per stage
#define DELTA 2
#define LOG2E 1.4426950408889634f
#define FULLM 0xffffffffu

static __device__ __forceinline__ float ex2f_(float x) {
    float y; asm("ex2.approx.ftz.f32 %0, %1;" : "=f"(y) : "f"(x)); return y;
}
static __device__ __forceinline__ float lg2f_(float x) {
    float y; asm("lg2.approx.ftz.f32 %0, %1;" : "=f"(y) : "f"(x)); return y;
}
static __device__ __forceinline__ void bar_s(int id, int cnt) {
    asm volatile("bar.sync %0, %1;" :: "r"(id), "r"(cnt) : "memory");
}
static __device__ __forceinline__ void bar_a(int id, int cnt) {
    asm volatile("bar.arrive %0, %1;" :: "r"(id), "r"(cnt) : "memory");
}
static __device__ __forceinline__ void st_dsmem64(unsigned daddr, unsigned long long v) {
    asm volatile("st.relaxed.cluster.shared::cluster.b64 [%0], %1;"
                 :: "r"(daddr), "l"(v) : "memory");
}

extern "C" __global__ void __launch_bounds__(NTHR, 1) __cluster_dims__(SUBS, 1, 1)
viterbi_fwd(const float* __restrict__ theta, float* __restrict__ out)
{
    extern __shared__ float4 Esm[];                         // EP * ESZ4 float4
    __shared__ __align__(16) unsigned long long sV[2][NS];  // tagged exp-domain V
    __shared__ float sEVv[2][NS];                           // renormalized V values
    __shared__ float sRed[2];

    const int tid  = threadIdx.x;
    const int lane = tid & 31;
    const int warp = tid >> 5;
    const int bid  = blockIdx.x;
    const int bb   = bid >> 2;
    const int sub  = bid & 3;

    unsigned vbase = (unsigned)__cvta_generic_to_shared(&sV[0][0]);

    // zero tags; init V_0 = 1 in exp domain
    for (int i = tid; i < 2 * NS; i += NTHR) ((unsigned long long*)sV)[i] = 0ull;
    if (tid < NCONS) { sEVv[0][2 * tid] = 1.f; sEVv[0][2 * tid + 1] = 1.f; }
    __syncthreads();
    asm volatile("barrier.cluster.arrive.aligned;" ::: "memory");
    asm volatile("barrier.cluster.wait.aligned;"   ::: "memory");

    if (tid < NCONS) {
        // ================= CONSUMER =================
        const int cl = tid;
        const int r  = cl >> 1;          // local row 0..31
        const int h  = cl & 1;           // which half of j
        const int irow = sub * 32 + r;

        unsigned rV[SUBS];
#pragma unroll
        for (int rr = 0; rr < SUBS; ++rr)
            asm("mapa.shared::cluster.u32 %0, %1, %2;" : "=r"(rV[rr]) : "r"(vbase), "r"(rr));

        float off = 0.f;
        const unsigned pollA = vbase + (unsigned)(2 * cl * 8);   // + par*NS*8

        for (int t = 0; t < NT; ++t) {
            const int par = t & 1;
            const int k   = t & 3;

            bar_s(2 + k, NTHR);          // E stage t ready

            if (t > 0) {
                unsigned a = pollA + (unsigned)(par * NS * 8);
                unsigned x0, t0, x1, t1;
                do {
                    asm volatile("ld.volatile.shared.v4.u32 {%0,%1,%2,%3}, [%4];"
                                 : "=r"(x0), "=r"(t0), "=r"(x1), "=r"(t1) : "r"(a));
                } while (t0 != (unsigned)t || t1 != (unsigned)t);
                unsigned z0, zt;
                unsigned a0 = vbase + (unsigned)(par * NS * 8);
                do {
                    asm volatile("ld.volatile.shared.v2.u32 {%0,%1}, [%2];"
                                 : "=r"(z0), "=r"(zt) : "r"(a0));
                } while (zt != (unsigned)t);
                int roff = (int)((z0 >> 23) & 0xFF) - 127;
                float scale = __uint_as_float((unsigned)(127 - roff) << 23);
                sEVv[par][2 * cl]     = __uint_as_float(x0) * scale;
                sEVv[par][2 * cl + 1] = __uint_as_float(x1) * scale;
                off += (float)roff;
            }
            bar_s(14, NCONS);            // consumer-local: sEVv[par] complete

            // half-row dot: j = 64h .. 64h+63
            const float4* Ep = Esm + (size_t)k * ESZ4 + r * ESTR4 + h * 16;
            const float4* Vp = ((const float4*)sEVv[par]) + h * 16;
            float a0 = 0.f, a1 = 0.f, a2 = 0.f, a3 = 0.f;
#pragma unroll
            for (int c = 0; c < 16; ++c) {
                float4 e = Ep[c];
                float4 v = Vp[c];
                a0 = fmaf(e.x, v.x, a0);
                a1 = fmaf(e.y, v.y, a1);
                a2 = fmaf(e.z, v.z, a2);
                a3 = fmaf(e.w, v.w, a3);
            }
            float c = (a0 + a1) + (a2 + a3);
            c += __shfl_xor_sync(FULLM, c, 1);   // combine the two halves

            bar_a(8 + k, NTHR);          // E stage t consumed

            unsigned long long pkt = ((unsigned long long)(unsigned)(t + 1) << 32)
                                   | (unsigned long long)__float_as_uint(c);
            unsigned voff = (unsigned)((((t + 1) & 1) * NS + irow) * 8);
            st_dsmem64(rV[2 * h]     + voff, pkt);
            st_dsmem64(rV[2 * h + 1] + voff, pkt);
        }

        // ---- epilogue: V_NT (tag NT) on parity 0; rank 0 reduces ----
        if (sub == 0) {
            unsigned a = pollA;   // parity 0
            unsigned x0, t0, x1, t1;
            do {
                asm volatile("ld.volatile.shared.v4.u32 {%0,%1,%2,%3}, [%4];"
                             : "=r"(x0), "=r"(t0), "=r"(x1), "=r"(t1) : "r"(a));
            } while (t0 != (unsigned)NT || t1 != (unsigned)NT);
            float part = __uint_as_float(x0) + __uint_as_float(x1);
#pragma unroll
            for (int o = 16; o; o >>= 1) part += __shfl_xor_sync(FULLM, part, o);
            if (lane == 0) sRed[warp] = part;
            bar_s(14, NCONS);
            if (tid == 0)
                out[bb] = 0.6931471805599453f * (off + lg2f_(sRed[0] + sRed[1]));
        }
    } else {
        // ================= PRODUCER =================
        const int ptid = tid - NCONS;      // 0..127
        const int p    = ptid >> 5;        // producer warp 0..3
        const size_t ts4 = (size_t)NB * NS * NS / 4;   // float4 per timestep
        const float4* gbase = (const float4*)
            (theta + ((size_t)bb * NS + (size_t)sub * 32) * NS);

        float4 buf[DELTA][8];
#pragma unroll
        for (int d = 0; d < DELTA; ++d)
#pragma unroll
            for (int m = 0; m < 8; ++m)
                buf[d][m] = __ldg(gbase + (size_t)d * ts4 + ptid + 128 * m);

        for (int s = 0; s < NT; ++s) {
            const int k = s & 3;
            if (s >= EP) bar_s(8 + k, NTHR);           // stage slot free

            float4* Ep = Esm + (size_t)k * ESZ4 + lane;
#pragma unroll
            for (int m = 0; m < 8; ++m) {
                float4 v = buf[s & 1][m];
                float4 e;
                e.x = ex2f_(v.x * LOG2E);
                e.y = ex2f_(v.y * LOG2E);
                e.z = ex2f_(v.z * LOG2E);
                e.w = ex2f_(v.w * LOG2E);
                Ep[(p + 4 * m) * ESTR4] = e;           // row p+4m, col4 = lane
            }
            bar_a(2 + k, NTHR);                        // stage s full

            if (s + DELTA < NT) {
#pragma unroll
                for (int m = 0; m < 8; ++m)
                    buf[s & 1][m] = __ldg(gbase + (size_t)(s + DELTA) * ts4
                                          + ptid + 128 * m);
            }
        }
    }

    asm volatile("barrier.cluster.arrive.aligned;" ::: "memory");
    asm volatile("barrier.cluster.wait.aligned;"   ::: "memory");
}

extern "C" void kernel_launch(void* const* d_in, const int* in_sizes, int n_in,
                              void* d_out, int out_size)
{
    (void)in_sizes; (void)n_in; (void)out_size;
    const float* theta = (const float*)d_in[0];
    float* out = (float*)d_out;

    cudaFuncSetAttribute(viterbi_fwd,
                         cudaFuncAttributeMaxDynamicSharedMemorySize,
                         EP * ESZ4 * 16);
    viterbi_fwd<<<NB * SUBS, NTHR, EP * ESZ4 * 16>>>(theta, out);
}

// round 8
// speedup vs baseline: 1.9639x; 1.9639x over previous
#include <cuda_runtime.h>
#include <cstdint>

// PackedViterbi (logsumexp semiring) forward — R4 skeleton + exp-domain relay.
// theta: [T=256, B=32, S=128, S=128] fp32.  out: [B=32] fp32.
//
// 32 clusters x 4 CTAs (one per batch), 256 threads per CTA, 32 rows each.
// V is relayed in the EXP DOMAIN as tagged 8-byte DSMEM packets {tag,val}.
// Per step: one volatile LDS.64 poll per thread (own slot), one __syncthreads,
// then lanes read the 16 packets their dot needs with plain LDS.128 (tags are
// guaranteed after the barrier). Renormalization = one multiply by 2^-roff
// after the reduce (roff = slot-0 exponent); off accumulates as int.
// No ex2/lg2 anywhere on the serial chain.

#define NT   256
#define NB   32
#define NS   128
#define SUBS 4
#define RPC  32
#define NTHR 256
#define TILE_BYTES (RPC * NS * 4)    // 16384
#define PIPE 6
#define DIST 4
#define LOG2E 1.4426950408889634f
#define FULLM 0xffffffffu

static __device__ __forceinline__ float ex2f_(float x) {
    float y; asm("ex2.approx.ftz.f32 %0, %1;" : "=f"(y) : "f"(x)); return y;
}
static __device__ __forceinline__ float lg2f_(float x) {
    float y; asm("lg2.approx.ftz.f32 %0, %1;" : "=f"(y) : "f"(x)); return y;
}
static __device__ __forceinline__ void cp16(unsigned d, const void* s) {
    asm volatile("cp.async.cg.shared.global [%0], [%1], 16;" :: "r"(d), "l"(s));
}
static __device__ __forceinline__ void st_dsmem64(unsigned daddr, unsigned long long v) {
    asm volatile("st.relaxed.cluster.shared::cluster.b64 [%0], %1;"
                 :: "r"(daddr), "l"(v) : "memory");
}

extern "C" __global__ void __launch_bounds__(NTHR, 1) __cluster_dims__(SUBS, 1, 1)
viterbi_fwd(const float* __restrict__ theta, float* __restrict__ out)
{
    extern __shared__ float4 ring[];                         // PIPE * 1024 float4
    __shared__ __align__(16) unsigned long long sV[2][NS];   // tagged exp-domain V

    const int tid  = threadIdx.x;
    const int lane = tid & 31;
    const int warp = tid >> 5;
    const int sl   = lane & 7;          // 8 lanes per row
    const int rg   = lane >> 3;
    const int rowL = (warp << 2) + rg;  // local row 0..31
    const int bid  = blockIdx.x;
    const int bb   = bid >> 2;          // batch
    const int sub  = bid & 3;           // cluster rank
    const int irow = sub * RPC + rowL;  // global state index i

    unsigned rbase = (unsigned)__cvta_generic_to_shared(ring);
    unsigned vbase = (unsigned)__cvta_generic_to_shared(&sV[0][0]);

    // zero tags before any peer can write
    ((unsigned long long*)sV)[tid] = 0ull;
    __syncthreads();
    asm volatile("barrier.cluster.arrive.aligned;" ::: "memory");
    asm volatile("barrier.cluster.wait.aligned;"   ::: "memory");

    unsigned rV[SUBS];
#pragma unroll
    for (int r = 0; r < SUBS; ++r)
        asm("mapa.shared::cluster.u32 %0, %1, %2;" : "=r"(rV[r]) : "r"(vbase), "r"(r));

    const size_t tstride = (size_t)NB * NS * NS;
    const float* base = theta + ((size_t)bb * NS + (size_t)sub * RPC) * NS;
    const int woff = warp * 2048;       // this warp's 4-row region within a tile

    // ---- prologue: each warp prefetches ITS OWN rows of stages 0..DIST-1 ----
#pragma unroll
    for (int s = 0; s < DIST; ++s) {
        const char* src = (const char*)(base + (size_t)s * tstride);
        unsigned dst = rbase + s * TILE_BYTES;
#pragma unroll
        for (int k2 = 0; k2 < 4; ++k2) {
            int o = woff + ((lane + 32 * k2) << 4);
            cp16(dst + o, src + o);
        }
        asm volatile("cp.async.commit_group;");
    }

    float Ea[16], Eb[16];
    int   off = 0;

    // stage 0 -> Ea
    asm volatile("cp.async.wait_group 3;");
    {
        const float4* tp = ring + rowL * (NS / 4) + sl;
        float4 a0 = tp[0], a1 = tp[8], a2 = tp[16], a3 = tp[24];
        Ea[0]  = ex2f_(a0.x * LOG2E); Ea[1]  = ex2f_(a0.y * LOG2E);
        Ea[2]  = ex2f_(a0.z * LOG2E); Ea[3]  = ex2f_(a0.w * LOG2E);
        Ea[4]  = ex2f_(a1.x * LOG2E); Ea[5]  = ex2f_(a1.y * LOG2E);
        Ea[6]  = ex2f_(a1.z * LOG2E); Ea[7]  = ex2f_(a1.w * LOG2E);
        Ea[8]  = ex2f_(a2.x * LOG2E); Ea[9]  = ex2f_(a2.y * LOG2E);
        Ea[10] = ex2f_(a2.z * LOG2E); Ea[11] = ex2f_(a2.w * LOG2E);
        Ea[12] = ex2f_(a3.x * LOG2E); Ea[13] = ex2f_(a3.y * LOG2E);
        Ea[14] = ex2f_(a3.z * LOG2E); Ea[15] = ex2f_(a3.w * LOG2E);
    }

    auto step = [&](int t, int par, float (&Ecur)[16], float (&Enext)[16]) {
        // 1. stage t+1 ready (own rows); prefetch own rows of t+DIST
        asm volatile("cp.async.wait_group 2;");
        if (t + DIST < NT) {
            const char* src = (const char*)(base + (size_t)(t + DIST) * tstride);
            unsigned dst = rbase + ((t + DIST) % PIPE) * TILE_BYTES;
#pragma unroll
            for (int k2 = 0; k2 < 4; ++k2) {
                int o = woff + ((lane + 32 * k2) << 4);
                cp16(dst + o, src + o);
            }
        }
        asm volatile("cp.async.commit_group;");

        // 2. transform stage t+1 -> Enext (covers the DSMEM transit window)
        if (t + 1 < NT) {
            const float4* tp = ring + ((t + 1) % PIPE) * (TILE_BYTES / 16)
                             + rowL * (NS / 4) + sl;
            float4 a0 = tp[0], a1 = tp[8], a2 = tp[16], a3 = tp[24];
            Enext[0]  = ex2f_(a0.x * LOG2E); Enext[1]  = ex2f_(a0.y * LOG2E);
            Enext[2]  = ex2f_(a0.z * LOG2E); Enext[3]  = ex2f_(a0.w * LOG2E);
            Enext[4]  = ex2f_(a1.x * LOG2E); Enext[5]  = ex2f_(a1.y * LOG2E);
            Enext[6]  = ex2f_(a1.z * LOG2E); Enext[7]  = ex2f_(a1.w * LOG2E);
            Enext[8]  = ex2f_(a2.x * LOG2E); Enext[9]  = ex2f_(a2.y * LOG2E);
            Enext[10] = ex2f_(a2.z * LOG2E); Enext[11] = ex2f_(a2.w * LOG2E);
            Enext[12] = ex2f_(a3.x * LOG2E); Enext[13] = ex2f_(a3.y * LOG2E);
            Enext[14] = ex2f_(a3.z * LOG2E); Enext[15] = ex2f_(a3.w * LOG2E);
        }

        // 3. poll OWN slot (one volatile LDS.64 per thread), then barrier
        if (t > 0 && tid < NS) {
            unsigned a = vbase + (unsigned)((par * NS + tid) * 8);
            unsigned vv, tg;
            do {
                asm volatile("ld.volatile.shared.v2.u32 {%0,%1}, [%2];"
                             : "=r"(vv), "=r"(tg) : "r"(a));
            } while (tg != (unsigned)t);
        }
        __syncthreads();

        // 4. direct packet reads + dot (tags guaranteed == t after barrier)
        float c;
        int roff = 0;
        if (t == 0) {
            c = ((Ecur[0] + Ecur[1]) + (Ecur[2] + Ecur[3]))
              + ((Ecur[4] + Ecur[5]) + (Ecur[6] + Ecur[7]))
              + ((Ecur[8] + Ecur[9]) + (Ecur[10] + Ecur[11]))
              + ((Ecur[12] + Ecur[13]) + (Ecur[14] + Ecur[15]));
        } else {
            const uint4* P = (const uint4*)&sV[par][0];   // 16B = 2 packets
            unsigned v0b = (unsigned)sV[par][0];
            roff = (int)((v0b >> 23) & 0xFF) - 127;
            float a0 = 0.f, a1 = 0.f, a2 = 0.f, a3 = 0.f;
#pragma unroll
            for (int k = 0; k < 4; ++k) {
                uint4 q0 = P[16 * k + 2 * sl];        // j = 32k+4sl+0,1
                uint4 q1 = P[16 * k + 2 * sl + 1];    // j = 32k+4sl+2,3
                a0 = fmaf(Ecur[4 * k + 0], __uint_as_float(q0.x), a0);
                a1 = fmaf(Ecur[4 * k + 1], __uint_as_float(q0.z), a1);
                a2 = fmaf(Ecur[4 * k + 2], __uint_as_float(q1.x), a2);
                a3 = fmaf(Ecur[4 * k + 3], __uint_as_float(q1.z), a3);
            }
            c = (a0 + a1) + (a2 + a3);
        }

        // 5. 8-lane reduce, renorm, parallel fan-out send
        c += __shfl_xor_sync(FULLM, c, 1);
        c += __shfl_xor_sync(FULLM, c, 2);
        c += __shfl_xor_sync(FULLM, c, 4);

        if (t > 0) {
            off += roff;
            c *= __uint_as_float((unsigned)(127 - roff) << 23);   // * 2^-roff
        }
        if (sl < SUBS) {
            unsigned long long pkt = ((unsigned long long)(unsigned)(t + 1) << 32)
                                   | (unsigned long long)__float_as_uint(c);
            unsigned voff = (unsigned)((((t + 1) & 1) * NS + irow) * 8);
            st_dsmem64(rV[sl] + voff, pkt);
        }
    };

    for (int t = 0; t < NT; t += 2) {
        step(t,     0, Ea, Eb);
        step(t + 1, 1, Eb, Ea);
    }

    // ---- epilogue: drain tag NT (parity 0), then rank 0 reduces ----
    if (tid < NS) {
        unsigned ad = vbase + (unsigned)(tid * 8);
        unsigned vv, tg;
        do {
            asm volatile("ld.volatile.shared.v2.u32 {%0,%1}, [%2];"
                         : "=r"(vv), "=r"(tg) : "r"(ad));
        } while (tg != (unsigned)NT);
    }
    __syncthreads();
    if (sub == 0 && warp == 0) {
        float x0 = __uint_as_float((unsigned)sV[0][lane]);
        float x1 = __uint_as_float((unsigned)sV[0][lane + 32]);
        float x2 = __uint_as_float((unsigned)sV[0][lane + 64]);
        float x3 = __uint_as_float((unsigned)sV[0][lane + 96]);
        float s = (x0 + x1) + (x2 + x3);
#pragma unroll
        for (int o = 16; o; o >>= 1) s += __shfl_xor_sync(FULLM, s, o);
        if (lane == 0)
            out[bb] = 0.6931471805599453f * ((float)off + lg2f_(s));
    }
    asm volatile("barrier.cluster.arrive.aligned;" ::: "memory");
    asm volatile("barrier.cluster.wait.aligned;"   ::: "memory");
}

extern "C" void kernel_launch(void* const* d_in, const int* in_sizes, int n_in,
                              void* d_out, int out_size)
{
    (void)in_sizes; (void)n_in; (void)out_size;
    const float* theta = (const float*)d_in[0];
    float* out = (float*)d_out;

    cudaFuncSetAttribute(viterbi_fwd,
                         cudaFuncAttributeMaxDynamicSharedMemorySize,
                         PIPE * TILE_BYTES);
    viterbi_fwd<<<NB * SUBS, NTHR, PIPE * TILE_BYTES>>>(theta, out);
}